// round 3
// baseline (speedup 1.0000x reference)
#include <cuda_runtime.h>
#include <cstdint>

// MatrixFactorization: out[i] = dot(concat(Wd[dow], Wt[time], Wm[mon], Wy[day]), Wi[dest])
// N = 1048576, NUM_DIM = 32 per small table, NUM_FACTOR = 128, W_item = 100000 x 128.
//
// Strategy:
//  - 4 small tables (74 rows x 32 f32 = 9.5 KB) cached in shared memory per block.
//  - Warp-per-row: lane l owns factor elements [4l, 4l+4): item load is 1x LDG.128
//    (4 contiguous 128B lines), user load is 1x LDS.128 (each 8-lane phase covers
//    128 contiguous bytes of one table row -> conflict-free).
//  - Indices staged per 256-row tile into smem with coalesced loads.
//  - Butterfly shfl reduce; lane i keeps row i's sum -> one coalesced STG.32 per warp.

#define BLOCK 256
#define TILE  256              // rows per block
#define TAB_ROWS 74            // 7 + 24 + 12 + 31

__global__ __launch_bounds__(BLOCK) void mf_dot_kernel(
    const int* __restrict__ dow,  const int* __restrict__ tim,
    const int* __restrict__ mon,  const int* __restrict__ dayv,
    const int* __restrict__ dest,
    const float* __restrict__ Wd, const float* __restrict__ Wt,
    const float* __restrict__ Wm, const float* __restrict__ Wy,
    const float* __restrict__ Wi,
    float* __restrict__ out, int n)
{
    __shared__ __align__(16) float s_tab[TAB_ROWS * 32];
    __shared__ int s_idx[5][TILE];

    const int tid = threadIdx.x;

    // ---- cache the 4 small embedding tables in smem (coalesced) ----
    for (int j = tid; j < 7 * 32;  j += BLOCK) s_tab[j]            = Wd[j];
    for (int j = tid; j < 24 * 32; j += BLOCK) s_tab[7 * 32 + j]   = Wt[j];
    for (int j = tid; j < 12 * 32; j += BLOCK) s_tab[31 * 32 + j]  = Wm[j];
    for (int j = tid; j < 31 * 32; j += BLOCK) s_tab[43 * 32 + j]  = Wy[j];

    const int base  = blockIdx.x * TILE;
    const int valid = n - base;          // rows this block actually owns (<= TILE)

    // ---- stage this tile's indices (coalesced global reads) ----
    {
        const int g = base + tid;
        const bool ok = (tid < valid);
        s_idx[0][tid] = ok ? dow[g]  : 0;
        s_idx[1][tid] = ok ? tim[g]  : 0;
        s_idx[2][tid] = ok ? mon[g]  : 0;
        s_idx[3][tid] = ok ? dayv[g] : 0;
        s_idx[4][tid] = ok ? dest[g] : 0;
    }
    __syncthreads();

    const int warp = tid >> 5;
    const int lane = tid & 31;
    const int t    = lane >> 3;          // which small table (0..3)
    const int d    = (lane & 7) << 2;    // dim offset within table row (0,4,...,28)
    // table row bases: {0, 7, 31, 43} packed into a constant
    const int tb   = (0x2B1F0700u >> (t * 8)) & 0xFF;

    const int rbase = warp * 32;         // first tile-row of this warp
    float res = 0.0f;

    #pragma unroll 4
    for (int i = 0; i < 32; i++) {
        const int r    = rbase + i;
        const int uidx = s_idx[t][r];    // broadcast within 8-lane group
        const int di   = s_idx[4][r];    // broadcast within warp

        // item: 512B coalesced across the warp (4 x 128B lines), L2-resident gather
        const float4 it = __ldg(reinterpret_cast<const float4*>(
                              Wi + (size_t)di * 128) + lane);
        // user: conflict-free LDS.128 from cached tables
        const float4 us = *reinterpret_cast<const float4*>(
                              s_tab + (tb + uidx) * 32 + d);

        float p = it.x * us.x + it.y * us.y + it.z * us.z + it.w * us.w;
        p += __shfl_xor_sync(0xffffffffu, p, 16);
        p += __shfl_xor_sync(0xffffffffu, p, 8);
        p += __shfl_xor_sync(0xffffffffu, p, 4);
        p += __shfl_xor_sync(0xffffffffu, p, 2);
        p += __shfl_xor_sync(0xffffffffu, p, 1);
        if (lane == i) res = p;          // lane i keeps row i's result
    }

    // one coalesced 128B store per warp
    const int g = base + rbase + lane;
    if (g < n) out[g] = res;
}

extern "C" void kernel_launch(void* const* d_in, const int* in_sizes, int n_in,
                              void* d_out, int out_size)
{
    const int*   dow  = (const int*)d_in[0];
    const int*   tim  = (const int*)d_in[1];
    const int*   mon  = (const int*)d_in[2];
    const int*   dayv = (const int*)d_in[3];
    const int*   dest = (const int*)d_in[4];
    const float* Wd   = (const float*)d_in[5];
    const float* Wt   = (const float*)d_in[6];
    const float* Wm   = (const float*)d_in[7];
    const float* Wy   = (const float*)d_in[8];
    const float* Wi   = (const float*)d_in[9];
    float* out = (float*)d_out;

    const int n = in_sizes[0];
    const int grid = (n + TILE - 1) / TILE;
    mf_dot_kernel<<<grid, BLOCK>>>(dow, tim, mon, dayv, dest,
                                   Wd, Wt, Wm, Wy, Wi, out, n);
}

// round 5
// speedup vs baseline: 1.1474x; 1.1474x over previous
#include <cuda_runtime.h>
#include <cstdint>

// MatrixFactorization: out[i] = dot(concat(Wd[dow],Wt[time],Wm[mon],Wy[day]), Wi[dest])
// N=1048576, 4 small tables (74 rows x 32 f32) in smem, W_item 100000x128 (L2-resident).
//
// R3: MIO-wavefront diet (L1TEX was 84.5% SOL):
//  - indices packed to int2 per row -> one broadcast LDS.64 instead of two LDS.32
//  - 16-row transpose-reduce merge tree: ~1.94 shfl/row instead of 5/row;
//    result lands with row j in lane (j&15) of BOTH half-warps -> branch-free
//    coalesced store.

#define BLOCK 256
#define TILE  256
#define TAB_ROWS 74   // 7 + 24 + 12 + 31

// Merge two per-row partial vectors a (row A) and b (row B) with stride m:
// result holds row A's partial in lanes with (lane&m)==0, row B where !=0,
// each now additionally reduced over mask m. One shfl per merge.
__device__ __forceinline__ float mergef(float a, float b, int m, int lane)
{
    float snd = (lane & m) ? a : b;   // send the OTHER row's value
    float rcv = __shfl_xor_sync(0xffffffffu, snd, m);
    float kee = (lane & m) ? b : a;   // keep own row's value
    return kee + rcv;
}

__global__ __launch_bounds__(BLOCK) void mf_dot_kernel(
    const int* __restrict__ dow,  const int* __restrict__ tim,
    const int* __restrict__ mon,  const int* __restrict__ dayv,
    const int* __restrict__ dest,
    const float* __restrict__ Wd, const float* __restrict__ Wt,
    const float* __restrict__ Wm, const float* __restrict__ Wy,
    const float* __restrict__ Wi,
    float* __restrict__ out, int n)
{
    __shared__ __align__(16) float s_tab[TAB_ROWS * 32];
    __shared__ __align__(8)  int2  s_idx[TILE];

    const int tid = threadIdx.x;

    // ---- cache the 4 small embedding tables in smem (coalesced) ----
    for (int j = tid; j < 7 * 32;  j += BLOCK) s_tab[j]           = Wd[j];
    for (int j = tid; j < 24 * 32; j += BLOCK) s_tab[7 * 32 + j]  = Wt[j];
    for (int j = tid; j < 12 * 32; j += BLOCK) s_tab[31 * 32 + j] = Wm[j];
    for (int j = tid; j < 31 * 32; j += BLOCK) s_tab[43 * 32 + j] = Wy[j];

    const int base  = blockIdx.x * TILE;
    const int valid = n - base;

    // ---- stage packed indices: {dest, dow|time<<8|mon<<16|day<<24} ----
    {
        const int g = base + tid;
        if (tid < valid) {
            int p = dow[g] | (tim[g] << 8) | (mon[g] << 16) | (dayv[g] << 24);
            s_idx[tid] = make_int2(dest[g], p);
        } else {
            s_idx[tid] = make_int2(0, 0);
        }
    }
    __syncthreads();

    const int warp = tid >> 5;
    const int lane = tid & 31;
    const int t    = lane >> 3;               // small table id (0..3)
    const int d    = (lane & 7) << 2;         // dim offset within table row
    const int tb   = (0x2B1F0700u >> (t * 8)) & 0xFF;  // {0,7,31,43}
    const int toff = tb * 32 + d;             // lane-constant table offset
    const unsigned sel = 0x4440u | (unsigned)t; // PRMT selector: byte t -> low byte

    const int rbase = warp * 32;
    float res[2];

    #pragma unroll
    for (int h = 0; h < 2; h++) {
        float v[16];

        #pragma unroll
        for (int j = 0; j < 16; j++) {
            const int2 ix = s_idx[rbase + h * 16 + j];   // 1x LDS.64 broadcast
            const int uidx = (int)__byte_perm((unsigned)ix.y, 0u, sel);

            // item: 512B coalesced gather (4x128B lines), L2-resident
            const float4 it = __ldg(reinterpret_cast<const float4*>(
                                  Wi + (size_t)ix.x * 128) + lane);
            // user: conflict-free LDS.128 from cached tables
            const float4 us = *reinterpret_cast<const float4*>(
                                  s_tab + toff + uidx * 32);

            v[j] = it.x * us.x + it.y * us.y + it.z * us.z + it.w * us.w;
        }

        // mask-16 fold: halves become identical (preserved by later merges)
        #pragma unroll
        for (int j = 0; j < 16; j++)
            v[j] += __shfl_xor_sync(0xffffffffu, v[j], 16);

        // packing merge tree: after all levels, lane l holds row (l & 15)
        #pragma unroll
        for (int k = 0; k < 8; k++) v[k] = mergef(v[2*k], v[2*k+1], 1, lane);
        #pragma unroll
        for (int k = 0; k < 4; k++) v[k] = mergef(v[2*k], v[2*k+1], 2, lane);
        #pragma unroll
        for (int k = 0; k < 2; k++) v[k] = mergef(v[2*k], v[2*k+1], 4, lane);
        res[h] = mergef(v[0], v[1], 8, lane);
    }

    // lanes 0-15 hold rows rbase+0..15 (res[0]); lanes 16-31 hold rows
    // rbase+16..31 (res[1], since lane&15 maps directly). Fully coalesced.
    const int g = base + rbase + lane;
    if (g < n) out[g] = (lane < 16) ? res[0] : res[1];
}

extern "C" void kernel_launch(void* const* d_in, const int* in_sizes, int n_in,
                              void* d_out, int out_size)
{
    const int*   dow  = (const int*)d_in[0];
    const int*   tim  = (const int*)d_in[1];
    const int*   mon  = (const int*)d_in[2];
    const int*   dayv = (const int*)d_in[3];
    const int*   dest = (const int*)d_in[4];
    const float* Wd   = (const float*)d_in[5];
    const float* Wt   = (const float*)d_in[6];
    const float* Wm   = (const float*)d_in[7];
    const float* Wy   = (const float*)d_in[8];
    const float* Wi   = (const float*)d_in[9];
    float* out = (float*)d_out;

    const int n = in_sizes[0];
    const int grid = (n + TILE - 1) / TILE;
    mf_dot_kernel<<<grid, BLOCK>>>(dow, tim, mon, dayv, dest,
                                   Wd, Wt, Wm, Wy, Wi, out, n);
}

// round 6
// speedup vs baseline: 1.2376x; 1.0786x over previous
#include <cuda_runtime.h>
#include <cstdint>

// MatrixFactorization: out[i] = dot(concat(Wd[dow],Wt[time],Wm[mon],Wy[day]), Wi[dest])
// N=1048576, small tables (74x32 f32) in smem, W_item 100000x128 (L2-resident).
//
// R5: half-warp row-pair layout (L1TEX/MIO wavefront diet):
//  - lanes 0-15 own row p, lanes 16-31 own row p+16; each lane covers 8 dims
//    (4l and 64+4l) via 2x LDG.128 + 2x LDS.128 -> same compulsory wavefronts.
//  - reduction: single 15-merge packing tree per 32 rows (0.47 shfl/row,
//    was 2/row); final value for row l lands exactly in lane l -> branch-free
//    coalesced store.
//  - indices: one broadcast LDS.128 (int4 = both half-warps' packed indices)
//    per pair -> 0.5 wf/row (was 1).

#define BLOCK 256
#define TILE  256
#define TAB_ROWS 74   // 7 + 24 + 12 + 31

// Packing merge: combines per-row partials a (row A) and b (row B) over
// lane-mask m. Lanes with (lane&m)==0 end holding row A, others row B.
__device__ __forceinline__ float mergef(float a, float b, int m, int lane)
{
    float snd = (lane & m) ? a : b;   // send the OTHER row's value
    float rcv = __shfl_xor_sync(0xffffffffu, snd, m);
    float kee = (lane & m) ? b : a;
    return kee + rcv;
}

__global__ __launch_bounds__(BLOCK) void mf_dot_kernel(
    const int* __restrict__ dow,  const int* __restrict__ tim,
    const int* __restrict__ mon,  const int* __restrict__ dayv,
    const int* __restrict__ dest,
    const float* __restrict__ Wd, const float* __restrict__ Wt,
    const float* __restrict__ Wm, const float* __restrict__ Wy,
    const float* __restrict__ Wi,
    float* __restrict__ out, int n)
{
    __shared__ __align__(16) float s_tab[TAB_ROWS * 32];
    __shared__ __align__(16) int   s_idx[TILE * 2];   // int4 per row-pair

    const int tid = threadIdx.x;

    // ---- cache the 4 small embedding tables in smem (coalesced) ----
    for (int j = tid; j < 7 * 32;  j += BLOCK) s_tab[j]           = Wd[j];
    for (int j = tid; j < 24 * 32; j += BLOCK) s_tab[7 * 32 + j]  = Wt[j];
    for (int j = tid; j < 12 * 32; j += BLOCK) s_tab[31 * 32 + j] = Wm[j];
    for (int j = tid; j < 31 * 32; j += BLOCK) s_tab[43 * 32 + j] = Wy[j];

    const int base  = blockIdx.x * TILE;
    const int valid = n - base;

    // ---- stage packed indices interleaved per pair:
    //      pair p of warp w -> int4 { dest_p, pack_p, dest_{p+16}, pack_{p+16} }
    {
        const int g  = base + tid;
        const int w  = tid >> 5, rr = tid & 31;
        const int p  = rr & 15,  h  = rr >> 4;
        int dv = 0, pk = 0;
        if (tid < valid) {
            dv = dest[g];
            pk = dow[g] | (tim[g] << 8) | (mon[g] << 16) | (dayv[g] << 24);
        }
        int* dst = s_idx + ((w * 16 + p) << 2) + (h << 1);
        dst[0] = dv;
        dst[1] = pk;
    }
    __syncthreads();

    const int warp   = tid >> 5;
    const int lane   = tid & 31;
    const int lane15 = lane & 15;
    const int half   = lane >> 4;            // 0: row p, 1: row p+16
    const int t0     = lane15 >> 3;          // 0: dow/mon lanes, 1: time/day lanes
    const unsigned selA = 0x4440u | (unsigned)t0;        // byte t0   (dow/time)
    const unsigned selB = 0x4442u + (unsigned)t0;        // byte t0+2 (mon/day)
    const float* tabA = s_tab + (t0 ? 7  * 32 : 0)       + ((lane15 & 7) << 2);
    const float* tabB = s_tab + (t0 ? 43 * 32 : 31 * 32) + ((lane15 & 7) << 2);
    const int4*  idx4 = reinterpret_cast<const int4*>(s_idx) + warp * 16;
    const float4* WiV = reinterpret_cast<const float4*>(Wi);

    float v[16];

    #pragma unroll 4
    for (int p = 0; p < 16; p++) {
        const int4 q = idx4[p];                       // 1 broadcast LDS.128
        const int      di = half ? q.z : q.x;
        const unsigned pk = (unsigned)(half ? q.w : q.y);
        const int ua = (int)__byte_perm(pk, 0u, selA);
        const int ub = (int)__byte_perm(pk, 0u, selB);

        const float4* ip = WiV + (size_t)di * 32;
        const float4 iA = __ldg(ip + lane15);         // dims  4l..4l+3
        const float4 iB = __ldg(ip + 16 + lane15);    // dims 64+4l..+3
        const float4 uA = *reinterpret_cast<const float4*>(tabA + ua * 32);
        const float4 uB = *reinterpret_cast<const float4*>(tabB + ub * 32);

        v[p] = iA.x * uA.x + iA.y * uA.y + iA.z * uA.z + iA.w * uA.w
             + iB.x * uB.x + iB.y * uB.y + iB.z * uB.z + iB.w * uB.w;
    }

    // packing merge tree (within half-warps); row l ends in lane l
    #pragma unroll
    for (int k = 0; k < 8; k++) v[k] = mergef(v[2*k], v[2*k+1], 1, lane);
    #pragma unroll
    for (int k = 0; k < 4; k++) v[k] = mergef(v[2*k], v[2*k+1], 2, lane);
    #pragma unroll
    for (int k = 0; k < 2; k++) v[k] = mergef(v[2*k], v[2*k+1], 4, lane);
    const float res = mergef(v[0], v[1], 8, lane);

    const int g = base + warp * 32 + lane;
    if (g < n) out[g] = res;
}

extern "C" void kernel_launch(void* const* d_in, const int* in_sizes, int n_in,
                              void* d_out, int out_size)
{
    const int*   dow  = (const int*)d_in[0];
    const int*   tim  = (const int*)d_in[1];
    const int*   mon  = (const int*)d_in[2];
    const int*   dayv = (const int*)d_in[3];
    const int*   dest = (const int*)d_in[4];
    const float* Wd   = (const float*)d_in[5];
    const float* Wt   = (const float*)d_in[6];
    const float* Wm   = (const float*)d_in[7];
    const float* Wy   = (const float*)d_in[8];
    const float* Wi   = (const float*)d_in[9];
    float* out = (float*)d_out;

    const int n = in_sizes[0];
    const int grid = (n + TILE - 1) / TILE;
    mf_dot_kernel<<<grid, BLOCK>>>(dow, tim, mon, dayv, dest,
                                   Wd, Wt, Wm, Wy, Wi, out, n);
}